// round 8
// baseline (speedup 1.0000x reference)
#include <cuda_runtime.h>
#include <cuda_bf16.h>
#include <cstdint>
#include <cstring>

// MLP_Interpolate: 4x nearest upsample + 2-layer MLP.
// Base GEMM on tensor pipe via baseline-PTX mma.sync m16n8k16 bf16
// (3-term split Ah*Bh + Al*Bh + Ah*Bl, fp32 accum, residual ~1.5e-5 rel).
// 256 threads/CTA: 8 warps x M=16 MMA tiles; epilogue j-split 2 threads/pixel
// (thread s owns output rows j in {2s, 2s+1}) to double resident warps.

namespace {

typedef unsigned long long ull;

__device__ __forceinline__ ull pk(float lo, float hi) {
    ull r; asm("mov.b64 %0, {%1, %2};" : "=l"(r) : "f"(lo), "f"(hi)); return r;
}
__device__ __forceinline__ float2 upk(ull a) {
    float2 r; asm("mov.b64 {%0, %1}, %2;" : "=f"(r.x), "=f"(r.y) : "l"(a)); return r;
}
__device__ __forceinline__ ull addx2(ull a, ull b) {
    ull d; asm("add.rn.f32x2 %0, %1, %2;" : "=l"(d) : "l"(a), "l"(b)); return d;
}
__device__ __forceinline__ ull fmax2p(ull a, ull b, ull c) {
    ull d; asm("fma.rn.f32x2 %0, %1, %2, %3;" : "=l"(d) : "l"(a), "l"(b), "l"(c)); return d;
}
__device__ __forceinline__ ull relu2(ull v) {
    float2 t = upk(v);
    return pk(fmaxf(t.x, 0.f), fmaxf(t.y, 0.f));
}
__device__ __forceinline__ uint32_t s2u(const void* p) {
    uint32_t a;
    asm("{ .reg .u64 t; cvta.to.shared.u64 t, %1; cvt.u32.u64 %0, t; }" : "=r"(a) : "l"(p));
    return a;
}
__device__ __forceinline__ void ldsm4(uint32_t addr, uint32_t& r0, uint32_t& r1,
                                      uint32_t& r2, uint32_t& r3) {
    asm volatile("ldmatrix.sync.aligned.m8n8.x4.shared.b16 {%0,%1,%2,%3}, [%4];"
                 : "=r"(r0), "=r"(r1), "=r"(r2), "=r"(r3) : "r"(addr));
}
__device__ __forceinline__ void mma16816(float* d, const uint32_t* a,
                                         uint32_t b0, uint32_t b1) {
    asm volatile(
        "mma.sync.aligned.m16n8k16.row.col.f32.bf16.bf16.f32 "
        "{%0,%1,%2,%3}, {%4,%5,%6,%7}, {%8,%9}, {%0,%1,%2,%3};"
        : "+f"(d[0]), "+f"(d[1]), "+f"(d[2]), "+f"(d[3])
        : "r"(a[0]), "r"(a[1]), "r"(a[2]), "r"(a[3]), "r"(b0), "r"(b1));
}

constexpr int Hh = 128, Wd = 128, HW = Hh * Wd, OUT = 512;
constexpr int BSTR = 66;   // base_s row stride (floats)

// smem layout (bytes); base_s (128*66*4 = 33792) overlays A/B after MMA
constexpr int S_AHI = 0;            // X_hi  [128][64 bf16]  16384
constexpr int S_ALO = 16384;        // X_lo                  16384
constexpr int S_BHI = 32768;        // W1T_hi [64][64 bf16]   8192
constexpr int S_BLO = 40960;        // W1T_lo                 8192
constexpr int S_CP  = 49152;        // Cp[4][65] ulonglong2   4160
constexpr int S_W2P = S_CP + 4160;  // W2p[64] ulonglong2     1024
constexpr int S_W2Q = S_W2P + 1024; // W2q[64] ull             512
constexpr int S_B2  = S_W2Q + 512;  // b2[4]
constexpr int S_TOTAL = S_B2 + 16;  // 54864

// split 8 floats -> bf16-hi quad + bf16-lo quad (cheap: bf16x2 cvt + shift/mask)
__device__ __forceinline__ void pack8(const float* v, uint4& qh, uint4& ql) {
    uint32_t H[4], L[4];
    #pragma unroll
    for (int p = 0; p < 4; p++) {
        uint32_t hp;
        asm("cvt.rn.bf16x2.f32 %0, %1, %2;" : "=r"(hp) : "f"(v[2*p+1]), "f"(v[2*p]));
        const float h0 = __uint_as_float(hp << 16);
        const float h1 = __uint_as_float(hp & 0xffff0000u);
        const float l0 = v[2*p]   - h0;
        const float l1 = v[2*p+1] - h1;
        uint32_t lp;
        asm("cvt.rn.bf16x2.f32 %0, %1, %2;" : "=r"(lp) : "f"(l1), "f"(l0));
        H[p] = hp; L[p] = lp;
    }
    qh = make_uint4(H[0], H[1], H[2], H[3]);
    ql = make_uint4(L[0], L[1], L[2], L[3]);
}

__global__ __launch_bounds__(256, 3)
void mlp_interp_mma(const float* __restrict__ x, const float* __restrict__ W1,
                    const float* __restrict__ b1, const float* __restrict__ W2,
                    const float* __restrict__ b2, float* __restrict__ out)
{
    extern __shared__ char smem[];
    const uint32_t sb = s2u(smem);
    const int tid  = threadIdx.x;
    const int lane = tid & 31;
    const int wid  = tid >> 5;            // 0..7
    const int px   = tid >> 1;            // pixel 0..127
    const int s    = tid & 1;             // channel-half / j-half
    const int cta  = blockIdx.x;          // 512: (b, h)
    const int h = cta & (Hh - 1);
    const int b = cta >> 7;

    // ---- stage A: thread (px, s) packs channels [32s, 32s+32) of pixel px ----
    {
        const float* xp = x + ((size_t)b * 64 + 32 * s) * HW + h * Wd + px;
        #pragma unroll
        for (int qq = 0; qq < 4; qq++) {
            float v[8];
            #pragma unroll
            for (int c = 0; c < 8; c++) v[c] = xp[(size_t)(8 * qq + c) * HW];
            uint4 qhv, qlv;
            pack8(v, qhv, qlv);
            const int q = 4 * s + qq;
            const uint32_t off = (uint32_t)px * 128 + (uint32_t)((q ^ (px & 7)) << 4);
            *(uint4*)(smem + S_AHI + off) = qhv;
            *(uint4*)(smem + S_ALO + off) = qlv;
        }
    }

    if (tid >= 128) {
        // ---- stage B: thread (i, s2) packs W1[32s2..32s2+32][i] ----
        const int t2 = tid - 128;
        const int i  = t2 >> 1;
        const int s2 = t2 & 1;
        #pragma unroll
        for (int qq = 0; qq < 4; qq++) {
            float v[8];
            #pragma unroll
            for (int c = 0; c < 8; c++) v[c] = W1[(32 * s2 + 8 * qq + c) * 64 + i];
            uint4 qhv, qlv;
            pack8(v, qhv, qlv);
            const int q = 4 * s2 + qq;
            const uint32_t off = (uint32_t)i * 128 + (uint32_t)((q ^ (i & 7)) << 4);
            *(uint4*)(smem + S_BHI + off) = qhv;
            *(uint4*)(smem + S_BLO + off) = qlv;
        }
    } else if (tid < 64) {
        // ---- epilogue tables ----
        const int c = tid;
        const float w64 = W1[64 * 64 + c];
        const float w65 = W1[64 * 64 + 64 + c];
        const float bb  = b1[c];
        ulonglong2* Cp  = (ulonglong2*)(smem + S_CP);
        ulonglong2* W2p = (ulonglong2*)(smem + S_W2P);
        ull*        W2q = (ull*)(smem + S_W2Q);
        float*      b2s = (float*)(smem + S_B2);
        #pragma unroll
        for (int j = 0; j < 4; j++) {
            const float rj = -0.75f + 0.5f * (float)j;
            const float base = fmaf(rj, w64, bb);
            float cv[4];
            #pragma unroll
            for (int k = 0; k < 4; k++)
                cv[k] = fmaf(-0.75f + 0.5f * (float)k, w65, base);
            Cp[j * 65 + c].x = pk(cv[0], cv[1]);
            Cp[j * 65 + c].y = pk(cv[2], cv[3]);
        }
        const float w20 = W2[c * 3 + 0];
        const float w21 = W2[c * 3 + 1];
        const float w22 = W2[c * 3 + 2];
        W2p[c].x = pk(w20, w20);
        W2p[c].y = pk(w21, w21);
        W2q[c]   = pk(w22, w22);
        if (c < 3) b2s[c] = b2[c];
    }
    __syncthreads();

    // ---- MMA: warp wid owns pixel rows [16*wid, 16*wid+16) ----
    float dacc[8][4];
    #pragma unroll
    for (int nt = 0; nt < 8; nt++)
        #pragma unroll
        for (int r = 0; r < 4; r++) dacc[nt][r] = 0.f;

    {
        const int m0w = 16 * wid;
        const int rl  = lane & 15;
        const int qhh = lane >> 4;
        const int rx  = lane & 7;

        #pragma unroll
        for (int term = 0; term < 3; term++) {
            const uint32_t SA = sb + (term == 1 ? S_ALO : S_AHI);
            const uint32_t SB = sb + (term == 2 ? S_BLO : S_BHI);
            #pragma unroll
            for (int kt = 0; kt < 4; kt++) {
                const uint32_t kx = (uint32_t)(((2 * kt + qhh) ^ rx) << 4);
                uint32_t a0[4];
                ldsm4(SA + (uint32_t)(m0w + rl) * 128 + kx, a0[0], a0[1], a0[2], a0[3]);
                uint32_t bl0[8], bl1[8];
                #pragma unroll
                for (int ntp = 0; ntp < 4; ntp++) {
                    uint32_t r0, r1, r2, r3;
                    ldsm4(SB + (uint32_t)(16 * ntp + rl) * 128 + kx, r0, r1, r2, r3);
                    bl0[2 * ntp] = r0; bl0[2 * ntp + 1] = r1;
                    bl1[2 * ntp] = r2; bl1[2 * ntp + 1] = r3;
                }
                #pragma unroll
                for (int nt = 0; nt < 8; nt++)
                    mma16816(dacc[nt], a0, bl0[nt], bl1[nt]);
            }
        }
    }
    __syncthreads();   // all ldmatrix reads done before base_s overwrites A/B

    // ---- D fragments -> base_s[px][i] ----
    float* base_s = (float*)smem;
    {
        const int g = lane >> 2, tg = lane & 3;
        const int m = 16 * wid + g;
        #pragma unroll
        for (int nt = 0; nt < 8; nt++) {
            const int col = nt * 8 + 2 * tg;
            *(float2*)(base_s + m * BSTR + col) =
                make_float2(dacc[nt][0], dacc[nt][1]);
            *(float2*)(base_s + (m + 8) * BSTR + col) =
                make_float2(dacc[nt][2], dacc[nt][3]);
        }
    }
    __syncthreads();

    // ---- epilogue: thread (px, s) folds all 64 dims into rows j = 2s+jj ----
    const ulonglong2* Cp  = (const ulonglong2*)(smem + S_CP);
    const ulonglong2* W2p = (const ulonglong2*)(smem + S_W2P);
    const ull*        W2q = (const ull*)(smem + S_W2Q);
    const float*      b2s = (const float*)(smem + S_B2);
    const float*      brow = base_s + px * BSTR;
    const ulonglong2* cp0 = Cp + (2 * s) * 65;
    const ulonglong2* cp1 = cp0 + 65;

    ull acc[3][2][2];
    #pragma unroll
    for (int ch = 0; ch < 3; ch++) {
        const ull bv = pk(b2s[ch], b2s[ch]);
        acc[ch][0][0] = bv; acc[ch][0][1] = bv;
        acc[ch][1][0] = bv; acc[ch][1][1] = bv;
    }

    #pragma unroll 8
    for (int i = 0; i < 64; i++) {
        const float bs = brow[i];
        const ull bd = pk(bs, bs);
        const ulonglong2 wd01 = W2p[i];
        const ull        wdq  = W2q[i];
        #pragma unroll
        for (int jj = 0; jj < 2; jj++) {
            const ulonglong2 cc = (jj ? cp1 : cp0)[i];
            const ull h01 = relu2(addx2(bd, cc.x));
            const ull h23 = relu2(addx2(bd, cc.y));
            acc[0][jj][0] = fmax2p(h01, wd01.x, acc[0][jj][0]);
            acc[0][jj][1] = fmax2p(h23, wd01.x, acc[0][jj][1]);
            acc[1][jj][0] = fmax2p(h01, wd01.y, acc[1][jj][0]);
            acc[1][jj][1] = fmax2p(h23, wd01.y, acc[1][jj][1]);
            acc[2][jj][0] = fmax2p(h01, wdq,    acc[2][jj][0]);
            acc[2][jj][1] = fmax2p(h23, wdq,    acc[2][jj][1]);
        }
    }

    // ---- stores: out[b, ch, 4h + 2s + jj, 4*px .. 4*px+3] ----
    float4* op = (float4*)out;
    #pragma unroll
    for (int ch = 0; ch < 3; ch++) {
        #pragma unroll
        for (int jj = 0; jj < 2; jj++) {
            const float2 a0 = upk(acc[ch][jj][0]);
            const float2 a1 = upk(acc[ch][jj][1]);
            const size_t idx =
                ((size_t)(b * 3 + ch) * OUT + (4 * h + 2 * s + jj)) * (OUT / 4) + px;
            op[idx] = make_float4(a0.x, a0.y, a1.x, a1.y);
        }
    }
}

}  // namespace

extern "C" void kernel_launch(void* const* d_in, const int* in_sizes, int n_in,
                              void* d_out, int out_size) {
    const float* x  = (const float*)d_in[0];
    const float* W1 = (const float*)d_in[1];
    const float* b1 = (const float*)d_in[2];
    const float* W2 = (const float*)d_in[3];
    const float* b2 = (const float*)d_in[4];
    float* out = (float*)d_out;

    cudaFuncSetAttribute(mlp_interp_mma,
                         cudaFuncAttributeMaxDynamicSharedMemorySize, S_TOTAL);
    mlp_interp_mma<<<512, 256, S_TOTAL>>>(x, W1, b1, W2, b2, out);
}

// round 9
// speedup vs baseline: 1.0804x; 1.0804x over previous
#include <cuda_runtime.h>
#include <cuda_bf16.h>
#include <cstdint>
#include <cstring>

// MLP_Interpolate: 4x nearest upsample + 2-layer MLP.
// Base GEMM on tensor pipe via baseline-PTX mma.sync m16n8k16 bf16
// (3-term split Ah*Bh + Al*Bh + Ah*Bl, fp32 accum, residual ~1.5e-5 rel).
// 256 threads/CTA, epilogue j-split (thread s owns rows j in {2s,2s+1}).
// Epilogue computes C[j][k][i] on the fly from a warp-uniform 32B/i table
// (2 broadcast LDS.128) instead of the per-(j,i) Cp/W2 table loads.

namespace {

typedef unsigned long long ull;

__device__ __forceinline__ ull pk(float lo, float hi) {
    ull r; asm("mov.b64 %0, {%1, %2};" : "=l"(r) : "f"(lo), "f"(hi)); return r;
}
__device__ __forceinline__ float2 upk(ull a) {
    float2 r; asm("mov.b64 {%0, %1}, %2;" : "=f"(r.x), "=f"(r.y) : "l"(a)); return r;
}
__device__ __forceinline__ ull fmax2p(ull a, ull b, ull c) {
    ull d; asm("fma.rn.f32x2 %0, %1, %2, %3;" : "=l"(d) : "l"(a), "l"(b), "l"(c)); return d;
}
__device__ __forceinline__ ull relu2(ull v) {
    float2 t = upk(v);
    return pk(fmaxf(t.x, 0.f), fmaxf(t.y, 0.f));
}
__device__ __forceinline__ uint32_t s2u(const void* p) {
    uint32_t a;
    asm("{ .reg .u64 t; cvta.to.shared.u64 t, %1; cvt.u32.u64 %0, t; }" : "=r"(a) : "l"(p));
    return a;
}
__device__ __forceinline__ void ldsm4(uint32_t addr, uint32_t& r0, uint32_t& r1,
                                      uint32_t& r2, uint32_t& r3) {
    asm volatile("ldmatrix.sync.aligned.m8n8.x4.shared.b16 {%0,%1,%2,%3}, [%4];"
                 : "=r"(r0), "=r"(r1), "=r"(r2), "=r"(r3) : "r"(addr));
}
__device__ __forceinline__ void mma16816(float* d, const uint32_t* a,
                                         uint32_t b0, uint32_t b1) {
    asm volatile(
        "mma.sync.aligned.m16n8k16.row.col.f32.bf16.bf16.f32 "
        "{%0,%1,%2,%3}, {%4,%5,%6,%7}, {%8,%9}, {%0,%1,%2,%3};"
        : "+f"(d[0]), "+f"(d[1]), "+f"(d[2]), "+f"(d[3])
        : "r"(a[0]), "r"(a[1]), "r"(a[2]), "r"(a[3]), "r"(b0), "r"(b1));
}

constexpr int Hh = 128, Wd = 128, HW = Hh * Wd, OUT = 512;
constexpr int BSTR = 66;   // base_s row stride (floats)

// smem layout (bytes); base_s (128*66*4 = 33792) overlays A/B after MMA
constexpr int S_AHI = 0;            // X_hi  [128][64 bf16]  16384
constexpr int S_ALO = 16384;        // X_lo                  16384
constexpr int S_BHI = 32768;        // W1T_hi [64][64 bf16]   8192
constexpr int S_BLO = 40960;        // W1T_lo                 8192
constexpr int S_ET  = 49152;        // ET[64][8] floats       2048
constexpr int S_B2  = S_ET + 2048;  // b2[4]
constexpr int S_TOTAL = S_B2 + 16;  // 51216

// split 8 floats -> bf16-hi quad + bf16-lo quad
__device__ __forceinline__ void pack8(const float* v, uint4& qh, uint4& ql) {
    uint32_t H[4], L[4];
    #pragma unroll
    for (int p = 0; p < 4; p++) {
        uint32_t hp;
        asm("cvt.rn.bf16x2.f32 %0, %1, %2;" : "=r"(hp) : "f"(v[2*p+1]), "f"(v[2*p]));
        const float h0 = __uint_as_float(hp << 16);
        const float h1 = __uint_as_float(hp & 0xffff0000u);
        const float l0 = v[2*p]   - h0;
        const float l1 = v[2*p+1] - h1;
        uint32_t lp;
        asm("cvt.rn.bf16x2.f32 %0, %1, %2;" : "=r"(lp) : "f"(l1), "f"(l0));
        H[p] = hp; L[p] = lp;
    }
    qh = make_uint4(H[0], H[1], H[2], H[3]);
    ql = make_uint4(L[0], L[1], L[2], L[3]);
}

__global__ __launch_bounds__(256, 3)
void mlp_interp_mma(const float* __restrict__ x, const float* __restrict__ W1,
                    const float* __restrict__ b1, const float* __restrict__ W2,
                    const float* __restrict__ b2, float* __restrict__ out)
{
    extern __shared__ char smem[];
    const uint32_t sb = s2u(smem);
    const int tid  = threadIdx.x;
    const int lane = tid & 31;
    const int wid  = tid >> 5;            // 0..7
    const int px   = tid >> 1;            // pixel 0..127
    const int s    = tid & 1;             // j-half
    const int cta  = blockIdx.x;          // 512: (b, h)
    const int h = cta & (Hh - 1);
    const int b = cta >> 7;

    // ---- stage A: thread (px, s) packs channels [32s, 32s+32) of pixel px ----
    {
        const float* xp = x + ((size_t)b * 64 + 32 * s) * HW + h * Wd + px;
        #pragma unroll
        for (int qq = 0; qq < 4; qq++) {
            float v[8];
            #pragma unroll
            for (int c = 0; c < 8; c++) v[c] = xp[(size_t)(8 * qq + c) * HW];
            uint4 qhv, qlv;
            pack8(v, qhv, qlv);
            const int q = 4 * s + qq;
            const uint32_t off = (uint32_t)px * 128 + (uint32_t)((q ^ (px & 7)) << 4);
            *(uint4*)(smem + S_AHI + off) = qhv;
            *(uint4*)(smem + S_ALO + off) = qlv;
        }
    }

    if (tid >= 128) {
        // ---- stage B: thread (i, s2) packs W1[32s2..32s2+32][i] ----
        const int t2 = tid - 128;
        const int i  = t2 >> 1;
        const int s2 = t2 & 1;
        #pragma unroll
        for (int qq = 0; qq < 4; qq++) {
            float v[8];
            #pragma unroll
            for (int c = 0; c < 8; c++) v[c] = W1[(32 * s2 + 8 * qq + c) * 64 + i];
            uint4 qhv, qlv;
            pack8(v, qhv, qlv);
            const int q = 4 * s2 + qq;
            const uint32_t off = (uint32_t)i * 128 + (uint32_t)((q ^ (i & 7)) << 4);
            *(uint4*)(smem + S_BHI + off) = qhv;
            *(uint4*)(smem + S_BLO + off) = qlv;
        }
    } else if (tid < 64) {
        // ---- epilogue table: ET[i] = {u, v, b1, w20, w21, w22, 0, 0} ----
        const int c = tid;
        float4* ET4 = (float4*)(smem + S_ET);
        ET4[2 * c]     = make_float4(W1[64 * 64 + c], W1[64 * 64 + 64 + c],
                                     b1[c], 0.f);
        ET4[2 * c + 1] = make_float4(W2[c * 3 + 0], W2[c * 3 + 1],
                                     W2[c * 3 + 2], 0.f);
        if (c < 3) ((float*)(smem + S_B2))[c] = b2[c];
    }
    __syncthreads();

    // ---- MMA: warp wid owns pixel rows [16*wid, 16*wid+16) ----
    float dacc[8][4];
    #pragma unroll
    for (int nt = 0; nt < 8; nt++)
        #pragma unroll
        for (int r = 0; r < 4; r++) dacc[nt][r] = 0.f;

    {
        const int m0w = 16 * wid;
        const int rl  = lane & 15;
        const int qhh = lane >> 4;
        const int rx  = lane & 7;

        #pragma unroll
        for (int term = 0; term < 3; term++) {
            const uint32_t SA = sb + (term == 1 ? S_ALO : S_AHI);
            const uint32_t SB = sb + (term == 2 ? S_BLO : S_BHI);
            #pragma unroll
            for (int kt = 0; kt < 4; kt++) {
                const uint32_t kx = (uint32_t)(((2 * kt + qhh) ^ rx) << 4);
                uint32_t a0[4];
                ldsm4(SA + (uint32_t)(m0w + rl) * 128 + kx, a0[0], a0[1], a0[2], a0[3]);
                uint32_t bl0[8], bl1[8];
                #pragma unroll
                for (int ntp = 0; ntp < 4; ntp++) {
                    uint32_t r0, r1, r2, r3;
                    ldsm4(SB + (uint32_t)(16 * ntp + rl) * 128 + kx, r0, r1, r2, r3);
                    bl0[2 * ntp] = r0; bl0[2 * ntp + 1] = r1;
                    bl1[2 * ntp] = r2; bl1[2 * ntp + 1] = r3;
                }
                #pragma unroll
                for (int nt = 0; nt < 8; nt++)
                    mma16816(dacc[nt], a0, bl0[nt], bl1[nt]);
            }
        }
    }
    __syncthreads();   // all ldmatrix reads done before base_s overwrites A/B

    // ---- D fragments -> base_s[px][i] ----
    float* base_s = (float*)smem;
    {
        const int g = lane >> 2, tg = lane & 3;
        const int m = 16 * wid + g;
        #pragma unroll
        for (int nt = 0; nt < 8; nt++) {
            const int col = nt * 8 + 2 * tg;
            *(float2*)(base_s + m * BSTR + col) =
                make_float2(dacc[nt][0], dacc[nt][1]);
            *(float2*)(base_s + (m + 8) * BSTR + col) =
                make_float2(dacc[nt][2], dacc[nt][3]);
        }
    }
    __syncthreads();

    // ---- epilogue: rows j = 2s + {0,1}; C computed from uniform ET ----
    const float4* ET4 = (const float4*)(smem + S_ET);
    const float*  b2s = (const float*)(smem + S_B2);
    const float*  brow = base_s + px * BSTR;
    const float rj0 = -0.75f + 0.5f * (float)(2 * s);
    const float rj1 = rj0 + 0.5f;
    const ull RK01 = pk(-0.75f, -0.25f);
    const ull RK23 = pk(0.25f, 0.75f);

    ull acc[3][2][2];
    #pragma unroll
    for (int ch = 0; ch < 3; ch++) {
        const ull bv = pk(b2s[ch], b2s[ch]);
        acc[ch][0][0] = bv; acc[ch][0][1] = bv;
        acc[ch][1][0] = bv; acc[ch][1][1] = bv;
    }

    #pragma unroll 8
    for (int i = 0; i < 64; i++) {
        const float4 e0 = ET4[2 * i];        // {u, v, b1, -}   uniform
        const float4 e1 = ET4[2 * i + 1];    // {w20, w21, w22, -} uniform
        const float bs = brow[i];
        const float tb = bs + e0.z;
        const float t0 = fmaf(rj0, e0.x, tb);
        const float t1 = fmaf(rj1, e0.x, tb);
        const ull vd  = pk(e0.y, e0.y);
        const ull wd0 = pk(e1.x, e1.x);
        const ull wd1 = pk(e1.y, e1.y);
        const ull wd2 = pk(e1.z, e1.z);
        #pragma unroll
        for (int jj = 0; jj < 2; jj++) {
            const float tj = jj ? t1 : t0;
            const ull td = pk(tj, tj);
            const ull h01 = relu2(fmax2p(vd, RK01, td));
            const ull h23 = relu2(fmax2p(vd, RK23, td));
            acc[0][jj][0] = fmax2p(h01, wd0, acc[0][jj][0]);
            acc[0][jj][1] = fmax2p(h23, wd0, acc[0][jj][1]);
            acc[1][jj][0] = fmax2p(h01, wd1, acc[1][jj][0]);
            acc[1][jj][1] = fmax2p(h23, wd1, acc[1][jj][1]);
            acc[2][jj][0] = fmax2p(h01, wd2, acc[2][jj][0]);
            acc[2][jj][1] = fmax2p(h23, wd2, acc[2][jj][1]);
        }
    }

    // ---- stores: out[b, ch, 4h + 2s + jj, 4*px .. 4*px+3] ----
    float4* op = (float4*)out;
    #pragma unroll
    for (int ch = 0; ch < 3; ch++) {
        #pragma unroll
        for (int jj = 0; jj < 2; jj++) {
            const float2 a0 = upk(acc[ch][jj][0]);
            const float2 a1 = upk(acc[ch][jj][1]);
            const size_t idx =
                ((size_t)(b * 3 + ch) * OUT + (4 * h + 2 * s + jj)) * (OUT / 4) + px;
            op[idx] = make_float4(a0.x, a0.y, a1.x, a1.y);
        }
    }
}

}  // namespace

extern "C" void kernel_launch(void* const* d_in, const int* in_sizes, int n_in,
                              void* d_out, int out_size) {
    const float* x  = (const float*)d_in[0];
    const float* W1 = (const float*)d_in[1];
    const float* b1 = (const float*)d_in[2];
    const float* W2 = (const float*)d_in[3];
    const float* b2 = (const float*)d_in[4];
    float* out = (float*)d_out;

    cudaFuncSetAttribute(mlp_interp_mma,
                         cudaFuncAttributeMaxDynamicSharedMemorySize, S_TOTAL);
    mlp_interp_mma<<<512, 256, S_TOTAL>>>(x, W1, b1, W2, b2, out);
}